// round 4
// baseline (speedup 1.0000x reference)
#include <cuda_runtime.h>
#include <math.h>
#include <stdint.h>

typedef unsigned long long u64;

#define T_STEPS 1024
#define BATCH   64
#define DIM     512
#define G3      1536
#define NCTA    128
#define TPB     256
#define UPC     4
#define KC      128          // k-chunk staged in smem
#define WSTR    514          // u64 stride per weight column (padded vs 512 to kill bank conflicts)
#define NCOLS   36           // 12 (U0) + 12 (U1) + 12 (W1) gate columns per CTA

// ---------------- device scratch ----------------
__device__ float g_xg0[(size_t)T_STEPS * BATCH * G3];   // x@W0+bi0, [t][b][g]
__device__ float g_h0[2][BATCH * DIM];
__device__ float g_h1[2][BATCH * DIM];
__device__ unsigned g_count;
__device__ volatile unsigned g_gen;

// packed f32x2 fma: acc.{lo,hi} += a.{lo,hi} * b.{lo,hi}
#define FMA2(acc, a, b) \
    asm("fma.rn.f32x2 %0, %1, %2, %3;" : "=l"(acc) : "l"(a), "l"(b), "l"(acc))

__device__ __forceinline__ float2 unpk(u64 v) {
    float2 f;
    f.x = __uint_as_float((unsigned)v);          // low  = even row
    f.y = __uint_as_float((unsigned)(v >> 32));  // high = odd row
    return f;
}

// ---------------- grid-wide barrier (all 128 CTAs resident) ----------------
__device__ __forceinline__ void gbar(unsigned target) {
    __threadfence();
    __syncthreads();
    if (threadIdx.x == 0) {
        unsigned arrived = atomicAdd(&g_count, 1u);
        if (arrived == NCTA - 1) {
            g_count = 0;
            __threadfence();
            atomicAdd((unsigned*)&g_gen, 1u);
        } else {
            while (g_gen < target) { }
        }
    }
    __syncthreads();
}

// ---------------- reset state each replay ----------------
__global__ void reset_kernel() {
    if (blockIdx.x == 0 && threadIdx.x == 0) { g_count = 0; g_gen = 0; }
    int i = blockIdx.x * blockDim.x + threadIdx.x;
    int stride = gridDim.x * blockDim.x;
    for (int j = i; j < BATCH * DIM; j += stride) {
        g_h0[0][j] = 0.0f;
        g_h1[0][j] = 0.0f;
    }
}

// ---------------- phase 1: XG0[t][b][g] = x[b][t][:] @ W0 + bi0 (FMA2) ----------------
// grid: (24 g-tiles of 64, 1024 t). Thread: 4 rows (2 pairs) x 4 cols via f32x2.
__global__ void __launch_bounds__(TPB) precompute_xg0(const float* __restrict__ x,
                                                      const float* __restrict__ W0,
                                                      const float* __restrict__ b0) {
    __shared__ __align__(16) float  xs[32 * 68];    // [k][b]
    __shared__ __align__(16) float2 wsd[32 * 66];   // [k][c] duplicated {w,w}

    const int t     = blockIdx.y;
    const int gbase = blockIdx.x * 64;
    const int tid   = threadIdx.x;
    const int tr = tid & 15, tc = tid >> 4;
    const int r0 = tr * 4, c0 = tc * 4;

    u64 acc[2][4] = {};   // [rowpair][col], zero-packed

    for (int kc = 0; kc < DIM; kc += 32) {
#pragma unroll
        for (int j = 0; j < 8; ++j) {
            int lin = tid + j * TPB;                 // 0..2047
            int bb = lin >> 5, klx = lin & 31;
            xs[klx * 68 + bb] =
                x[(size_t)bb * (T_STEPS * DIM) + (size_t)t * DIM + kc + klx];
            int kk = lin >> 6, cc = lin & 63;
            float w = W0[(size_t)(kc + kk) * G3 + gbase + cc];
            wsd[kk * 66 + cc] = make_float2(w, w);
        }
        __syncthreads();
        const u64* xp = (const u64*)xs;
        const ulonglong2* wp = (const ulonglong2*)wsd;
#pragma unroll
        for (int kk = 0; kk < 32; ++kk) {
            u64 a0 = xp[kk * 34 + tr * 2];
            u64 a1 = xp[kk * 34 + tr * 2 + 1];
            ulonglong2 w01 = wp[kk * 33 + tc * 2];
            ulonglong2 w23 = wp[kk * 33 + tc * 2 + 1];
            FMA2(acc[0][0], a0, w01.x); FMA2(acc[0][1], a0, w01.y);
            FMA2(acc[0][2], a0, w23.x); FMA2(acc[0][3], a0, w23.y);
            FMA2(acc[1][0], a1, w01.x); FMA2(acc[1][1], a1, w01.y);
            FMA2(acc[1][2], a1, w23.x); FMA2(acc[1][3], a1, w23.y);
        }
        __syncthreads();
    }

    float4 bias = *(const float4*)&b0[gbase + c0];
#pragma unroll
    for (int rp = 0; rp < 2; ++rp) {
        float2 v0 = unpk(acc[rp][0]), v1 = unpk(acc[rp][1]);
        float2 v2 = unpk(acc[rp][2]), v3 = unpk(acc[rp][3]);
        size_t o = ((size_t)t * BATCH + r0 + rp * 2) * G3 + gbase + c0;
        float4 ve = make_float4(v0.x + bias.x, v1.x + bias.y, v2.x + bias.z, v3.x + bias.w);
        *(float4*)&g_xg0[o] = ve;
        float4 vo = make_float4(v0.y + bias.x, v1.y + bias.y, v2.y + bias.z, v3.y + bias.w);
        *(float4*)&g_xg0[o + G3] = vo;
    }
}

// ---------------- phase 2: persistent recurrent loop (FMA2 everywhere) ----------------
// 128 CTAs x 256 threads. CTA owns 4 units.
// Phase A thread = (rowpair p 0..31, cg 0..7) where cg = layer*4+unit:
//   computes z,r,h gate dots of (2 rows, unit) against U0 (layer0) or U1 (layer1).
// Phase B thread = (warp wB 0..3 -> unit, lane pb -> rowpair): z,r,h of h0new@W1.
// Weights duplicated {w,w} in smem once (static): b-operand of f32x2 FMA, zero movs.
#define SMEM_BYTES ((NCOLS * WSTR * 2 + 2 * KC * 66) * 4)   // 215,616 B

__global__ void __launch_bounds__(TPB, 1)
gru_loop(const float* __restrict__ U0, const float* __restrict__ W1,
         const float* __restrict__ U1, const float* __restrict__ b0,
         const float* __restrict__ b1, float* __restrict__ out) {
    extern __shared__ __align__(16) float sm[];
    u64*   wd  = (u64*)sm;                      // NCOLS cols x WSTR u64 ({w,w} per k)
    float* hc0 = sm + NCOLS * WSTR * 2;         // staged h chunk [k][r], pad 66
    float* hc1 = hc0 + KC * 66;

    const int tid = threadIdx.x;
    const int cg  = tid & 7;        // layer*4 + unit
    const int p   = tid >> 3;       // rowpair 0..31
    const int u   = cg & 3;
    const int lyr = cg >> 2;
    const int ubase = blockIdx.x * UPC;
    const int ug  = ubase + u;
    const int wB  = tid >> 5;       // phase-B unit = warp id
    const int pb  = tid & 31;       // phase-B rowpair = lane

    // one-time duplicated-weight preload: col c = layer*12 + unit*3 + gate
    for (int idx = tid; idx < NCOLS * DIM; idx += TPB) {
        int c = idx >> 9, k = idx & 511;
        int g  = c % 3;
        int uu = (c / 3) & 3;
        const float* src = (c < 12) ? U0 : (c < 24 ? U1 : W1);
        float v = __ldg(src + (size_t)k * G3 + g * 512 + ubase + uu);
        ((float2*)(wd + (size_t)c * WSTR))[k] = make_float2(v, v);
    }
    const float br0z = b0[G3 + ug], br0r = b0[G3 + 512 + ug], br0h = b0[G3 + 1024 + ug];
    const float bi1z = b1[ug],      bi1r = b1[512 + ug],      bi1h = b1[1024 + ug];
    const float br1z = b1[G3 + ug], br1r = b1[G3 + 512 + ug], br1h = b1[G3 + 1024 + ug];
    __syncthreads();

    const u64* hbaseA = (const u64*)(lyr ? hc1 : hc0);
    const ulonglong2* wzA = (const ulonglong2*)(wd + (size_t)(cg * 3 + 0) * WSTR);
    const ulonglong2* wrA = (const ulonglong2*)(wd + (size_t)(cg * 3 + 1) * WSTR);
    const ulonglong2* whA = (const ulonglong2*)(wd + (size_t)(cg * 3 + 2) * WSTR);
    const int cB = (8 + wB) * 3;    // only dereferenced when wB < 4
    const ulonglong2* wzB = (const ulonglong2*)(wd + (size_t)(cB + 0) * WSTR);
    const ulonglong2* wrB = (const ulonglong2*)(wd + (size_t)(cB + 1) * WSTR);
    const ulonglong2* whB = (const ulonglong2*)(wd + (size_t)(cB + 2) * WSTR);

    unsigned gen = 0;

    for (int t = 0; t < T_STEPS; ++t) {
        const float* h0in  = g_h0[t & 1];
        float*       h0out = g_h0[(t + 1) & 1];
        const float* h1in  = g_h1[t & 1];
        float*       h1out = g_h1[(t + 1) & 1];

        // ---- phase A: hg0 = h0@U0 (layer0 threads), hg1 = h1@U1 (layer1 threads)
        u64 az = 0, ar = 0, ah = 0;
        for (int kc = 0; kc < DIM; kc += KC) {
#pragma unroll
            for (int j = 0; j < 32; ++j) {
                int lin = tid + j * TPB;          // 0..8191
                int rr = lin >> 7, klx = lin & 127;
                hc0[klx * 66 + rr] = __ldcg(h0in + rr * 512 + kc + klx);
                hc1[klx * 66 + rr] = __ldcg(h1in + rr * 512 + kc + klx);
            }
            __syncthreads();
            const u64* hp = hbaseA + p;
#pragma unroll 16
            for (int kk = 0; kk < KC; kk += 2) {
                u64 hA = hp[kk * 33];
                u64 hB = hp[kk * 33 + 33];
                int wi = (kc + kk) >> 1;
                ulonglong2 wz = wzA[wi], wr = wrA[wi], wh = whA[wi];
                FMA2(az, hA, wz.x); FMA2(az, hB, wz.y);
                FMA2(ar, hA, wr.x); FMA2(ar, hB, wr.y);
                FMA2(ah, hA, wh.x); FMA2(ah, hB, wh.y);
            }
            __syncthreads();
        }

        // ---- pointwise layer 0 (layer-0 threads own their 2 rows x 1 unit)
        if (lyr == 0) {
            float2 vz = unpk(az), vr = unpk(ar), vh = unpk(ah);
#pragma unroll
            for (int q = 0; q < 2; ++q) {
                int r = 2 * p + q;
                float hgz = q ? vz.y : vz.x;
                float hgr = q ? vr.y : vr.x;
                float hgh = q ? vh.y : vh.x;
                size_t xb = ((size_t)t * BATCH + r) * G3 + ug;
                float xz = __ldg(&g_xg0[xb]);
                float xr = __ldg(&g_xg0[xb + 512]);
                float xh = __ldg(&g_xg0[xb + 1024]);
                float z    = 1.f / (1.f + expf(-(xz + hgz + br0z)));
                float rg   = 1.f / (1.f + expf(-(xr + hgr + br0r)));
                float cand = tanhf(xh + rg * (hgh + br0h));
                float h0o  = __ldcg(h0in + r * 512 + ug);
                h0out[r * 512 + ug] = z * h0o + (1.f - z) * cand;
            }
        }
        gbar(++gen);   // publish h0_new

        // ---- phase B: xg1raw = h0_new @ W1 (warps 0-3 compute, all stage)
        u64 bz = 0, brv = 0, bh = 0;
        for (int kc = 0; kc < DIM; kc += KC) {
#pragma unroll
            for (int j = 0; j < 32; ++j) {
                int lin = tid + j * TPB;
                int rr = lin >> 7, klx = lin & 127;
                hc0[klx * 66 + rr] = __ldcg(h0out + rr * 512 + kc + klx);
            }
            __syncthreads();
            if (wB < 4) {
                const u64* hp = (const u64*)hc0 + pb;
#pragma unroll 16
                for (int kk = 0; kk < KC; kk += 2) {
                    u64 hA = hp[kk * 33];
                    u64 hB = hp[kk * 33 + 33];
                    int wi = (kc + kk) >> 1;
                    ulonglong2 wz = wzB[wi], wr = wrB[wi], wh = whB[wi];
                    FMA2(bz,  hA, wz.x); FMA2(bz,  hB, wz.y);
                    FMA2(brv, hA, wr.x); FMA2(brv, hB, wr.y);
                    FMA2(bh,  hA, wh.x); FMA2(bh,  hB, wh.y);
                }
            }
            __syncthreads();
        }

        // ---- exchange B-gates to the layer-1 gate owners, then pointwise layer 1
        float* ex = hc1;   // phase-A contents of hc1 are dead now
        if (wB < 4) {
            float2 vz = unpk(bz), vr = unpk(brv), vh = unpk(bh);
            int bidx = (wB * 32 + pb) * 6;
            ex[bidx + 0] = vz.x; ex[bidx + 1] = vz.y;
            ex[bidx + 2] = vr.x; ex[bidx + 3] = vr.y;
            ex[bidx + 4] = vh.x; ex[bidx + 5] = vh.y;
        }
        __syncthreads();
        if (lyr == 1) {
            float2 cz = unpk(az), cr = unpk(ar), ch = unpk(ah);
            int bidx = (u * 32 + p) * 6;
            float bz0 = ex[bidx + 0], bz1 = ex[bidx + 1];
            float br0 = ex[bidx + 2], br1v = ex[bidx + 3];
            float bh0 = ex[bidx + 4], bh1 = ex[bidx + 5];
#pragma unroll
            for (int q = 0; q < 2; ++q) {
                int r = 2 * p + q;
                float xz  = (q ? bz1  : bz0)  + bi1z;
                float xr  = (q ? br1v : br0)  + bi1r;
                float xh  = (q ? bh1  : bh0)  + bi1h;
                float hgz = (q ? cz.y : cz.x) + br1z;
                float hgr = (q ? cr.y : cr.x) + br1r;
                float hgh = (q ? ch.y : ch.x) + br1h;
                float z1    = 1.f / (1.f + expf(-(xz + hgz)));
                float r1    = 1.f / (1.f + expf(-(xr + hgr)));
                float cand1 = tanhf(xh + r1 * hgh);
                float h1o   = __ldcg(h1in + r * 512 + ug);
                float h1n   = z1 * h1o + (1.f - z1) * cand1;
                h1out[r * 512 + ug] = h1n;
                if (t == T_STEPS - 1) out[r * 512 + ug] = h1n;
            }
        }
        gbar(++gen);   // publish h1_new, gate next step
    }
}

// ---------------- launcher ----------------
extern "C" void kernel_launch(void* const* d_in, const int* in_sizes, int n_in,
                              void* d_out, int out_size) {
    const float* x  = (const float*)d_in[0];
    const float* W0 = (const float*)d_in[1];
    const float* U0 = (const float*)d_in[2];
    const float* b0 = (const float*)d_in[3];
    const float* W1 = (const float*)d_in[4];
    const float* U1 = (const float*)d_in[5];
    const float* b1 = (const float*)d_in[6];
    float* out = (float*)d_out;

    cudaFuncSetAttribute(gru_loop, cudaFuncAttributeMaxDynamicSharedMemorySize,
                         SMEM_BYTES);

    reset_kernel<<<32, 256>>>();
    precompute_xg0<<<dim3(24, 1024), TPB>>>(x, W0, b0);
    gru_loop<<<NCTA, TPB, SMEM_BYTES>>>(U0, W1, U1, b0, b1, out);
}

// round 7
// speedup vs baseline: 1.8085x; 1.8085x over previous
#include <cuda_runtime.h>
#include <math.h>
#include <stdint.h>

typedef unsigned long long u64;

#define T_STEPS 1024
#define BATCH   64
#define DIM     512
#define G3      1536
#define NCTA    128
#define TPB     256
#define RPC     32      // rows per CTA
#define UPCC    8       // units per CTA
#define HCH     132     // floats per chunk row (128 + 4 pad) -> conflict-free LDS.128
#define WKS     516     // floats per weight column; 9*516 mod 32 = 4 -> warps conflict-free
#define NCOLS   (UPCC * 9)   // 72 weight columns per CTA

// ---------------- device scratch ----------------
__device__ float g_xg0[(size_t)T_STEPS * G3 * BATCH];   // [t][gate][b] layout
__device__ float g_h0[2][BATCH * DIM];
__device__ float g_h1[2][BATCH * DIM];
__device__ unsigned g_count;
__device__ volatile unsigned g_gen;

#define FMA2(acc, a, b) \
    asm("fma.rn.f32x2 %0, %1, %2, %3;" : "=l"(acc) : "l"(a), "l"(b), "l"(acc))

__device__ __forceinline__ float sum2(u64 v) {
    return __uint_as_float((unsigned)v) + __uint_as_float((unsigned)(v >> 32));
}
__device__ __forceinline__ float sigf(float x) { return 1.f / (1.f + expf(-x)); }

// ---------------- grid-wide barrier (all 128 CTAs resident, smem forces 1/SM) ----
__device__ __forceinline__ void gbar(unsigned target) {
    __threadfence();
    __syncthreads();
    if (threadIdx.x == 0) {
        unsigned arrived = atomicAdd(&g_count, 1u);
        if (arrived == NCTA - 1) {
            g_count = 0;
            __threadfence();
            atomicAdd((unsigned*)&g_gen, 1u);
        } else {
            while (g_gen < target) { }
        }
    }
    __syncthreads();
}

// ---------------- dummies so ncu -s 5 -c 1 lands on gru_loop (launch #6) ------
__global__ void nop_kernel(int x) { if (x == 12345) g_count = 1u; }

// ---------------- reset per replay ----------------
__global__ void reset_kernel() {
    if (blockIdx.x == 0 && threadIdx.x == 0) { g_count = 0; g_gen = 0; }
    int i = blockIdx.x * blockDim.x + threadIdx.x;
    int stride = gridDim.x * blockDim.x;
    for (int j = i; j < BATCH * DIM; j += stride) {
        g_h0[1][j] = 0.0f;   // h0(-1), read at iter 0
        g_h1[0][j] = 0.0f;   // h1(-1), read at iter 1
    }
}

// ---------------- phase 1: XG0[t][g][b] = (x[b][t][:] @ W0 + bi0)  (FMA2) -----
__global__ void __launch_bounds__(TPB) precompute_xg0(const float* __restrict__ x,
                                                      const float* __restrict__ W0,
                                                      const float* __restrict__ b0) {
    __shared__ __align__(16) float  xs[32 * 68];    // [k][b] transposed
    __shared__ __align__(16) float2 wsd[32 * 66];   // [k][c] duplicated {w,w}

    const int t     = blockIdx.y;
    const int gbase = blockIdx.x * 64;
    const int tid   = threadIdx.x;
    const int tr = tid & 15, tc = tid >> 4;
    const int r0 = tr * 4, c0 = tc * 4;

    u64 acc[2][4] = {};

    for (int kc = 0; kc < DIM; kc += 32) {
#pragma unroll
        for (int j = 0; j < 8; ++j) {
            int lin = tid + j * TPB;
            int bb = lin >> 5, klx = lin & 31;
            xs[klx * 68 + bb] =
                x[(size_t)bb * (T_STEPS * DIM) + (size_t)t * DIM + kc + klx];
            int kk = lin >> 6, cc = lin & 63;
            float w = W0[(size_t)(kc + kk) * G3 + gbase + cc];
            wsd[kk * 66 + cc] = make_float2(w, w);
        }
        __syncthreads();
        const u64* xp = (const u64*)xs;
        const ulonglong2* wp = (const ulonglong2*)wsd;
#pragma unroll
        for (int kk = 0; kk < 32; ++kk) {
            u64 a0 = xp[kk * 34 + tr * 2];
            u64 a1 = xp[kk * 34 + tr * 2 + 1];
            ulonglong2 w01 = wp[kk * 33 + tc * 2];
            ulonglong2 w23 = wp[kk * 33 + tc * 2 + 1];
            FMA2(acc[0][0], a0, w01.x); FMA2(acc[0][1], a0, w01.y);
            FMA2(acc[0][2], a0, w23.x); FMA2(acc[0][3], a0, w23.y);
            FMA2(acc[1][0], a1, w01.x); FMA2(acc[1][1], a1, w01.y);
            FMA2(acc[1][2], a1, w23.x); FMA2(acc[1][3], a1, w23.y);
        }
        __syncthreads();
    }

    float4 bias = *(const float4*)&b0[gbase + c0];
    float bi[4] = {bias.x, bias.y, bias.z, bias.w};
#pragma unroll
    for (int rp = 0; rp < 2; ++rp) {
#pragma unroll
        for (int i = 0; i < 4; ++i) {
            float2 v;
            v.x = __uint_as_float((unsigned)acc[rp][i]) + bi[i];
            v.y = __uint_as_float((unsigned)(acc[rp][i] >> 32)) + bi[i];
            // rows (r0+2rp, r0+2rp+1), col gbase+c0+i -> [t][g][b] layout
            size_t o = ((size_t)t * G3 + gbase + c0 + i) * BATCH + r0 + 2 * rp;
            *(float2*)&g_xg0[o] = v;
        }
    }
}

// ---------------- phase 2: pipelined persistent loop ----------------
// iter t (0..1024): compute h0(t) [t<1024] and h1(t-1) [t>=1].
// CTA = 8 units x 32 rows: ubase = (bid>>1)*8, rbase = (bid&1)*32.
// Thread: warp = unit (weight LDS broadcast), lane = row.
// Per thread: 9 dots (U0 z/r/h on h0, U1 z/r/h on h1, W1 z/r/h on h0); both
// pointwise updates thread-local. One grid barrier per iter.
// smem: weights 72*516, h chunks double-buffered 4 x 32*132.
#define SMEM_FLOATS (NCOLS * WKS + 4 * RPC * HCH)
#define SMEM_BYTES  (SMEM_FLOATS * 4)    // 216,192 B

__global__ void __launch_bounds__(TPB, 1)
gru_loop(const float* __restrict__ U0, const float* __restrict__ W1,
         const float* __restrict__ U1, const float* __restrict__ b0,
         const float* __restrict__ b1, float* __restrict__ out) {
    extern __shared__ __align__(16) float sm[];
    float* ws = sm;                                  // [72][516]
    float* hb0[2] = { sm + NCOLS * WKS,              // h0 chunk ping
                      sm + NCOLS * WKS + RPC * HCH };        // pong
    float* hb1[2] = { sm + NCOLS * WKS + 2 * RPC * HCH,
                      sm + NCOLS * WKS + 3 * RPC * HCH };

    const int tid    = threadIdx.x;
    const int u_loc  = tid >> 5;          // 0..7  (warp)
    const int r_loc  = tid & 31;          // 0..31 (lane)
    const int ubase  = (blockIdx.x >> 1) * UPCC;
    const int rbase  = (blockIdx.x & 1) * RPC;
    const int ug     = ubase + u_loc;
    const int rg     = rbase + r_loc;

    // one-time weight preload: col c = u_loc*9 + j; j 0-2:U0 z/r/h, 3-5:U1, 6-8:W1
    for (int idx = tid; idx < NCOLS * DIM; idx += TPB) {
        int c = idx >> 9, k = idx & 511;
        int uu = c / 9, j = c % 9;
        const float* mat = (j < 3) ? U0 : (j < 6 ? U1 : W1);
        int gate = j % 3;
        ws[c * WKS + k] = __ldg(mat + (size_t)k * G3 + gate * 512 + ubase + uu);
    }
    const float br0z = b0[G3 + ug], br0r = b0[G3 + 512 + ug], br0h = b0[G3 + 1024 + ug];
    const float bi1z = b1[ug],      bi1r = b1[512 + ug],      bi1h = b1[1024 + ug];
    const float br1z = b1[G3 + ug], br1r = b1[G3 + 512 + ug], br1h = b1[G3 + 1024 + ug];
    __syncthreads();

    const float* wcol = ws + (size_t)u_loc * 9 * WKS;   // 9 columns for this unit
    unsigned gen = 0;

    for (int t = 0; t <= T_STEPS; ++t) {
        const float* h0in  = g_h0[(t + 1) & 1];   // h0(t-1)
        const float* h1in  = g_h1[(t + 1) & 1];   // h1(t-2)
        float*       h0out = g_h0[t & 1];
        float*       h1out = g_h1[t & 1];

        // stage chunk 0 (rows rbase..rbase+31, k 0..127)
        {
            float4 v[8];
#pragma unroll
            for (int j = 0; j < 8; ++j) {
                int idx = tid + j * TPB;             // 0..2047
                int arr = idx >> 10, w = idx & 1023;
                int row = w >> 5, k4 = w & 31;
                const float* src = (arr ? h1in : h0in) + (rbase + row) * 512 + k4 * 4;
                v[j] = __ldcg((const float4*)src);
            }
#pragma unroll
            for (int j = 0; j < 8; ++j) {
                int idx = tid + j * TPB;
                int arr = idx >> 10, w = idx & 1023;
                int row = w >> 5, k4 = w & 31;
                *(float4*)&(arr ? hb1[0] : hb0[0])[row * HCH + k4 * 4] = v[j];
            }
        }

        // gate-input prefetch (coalesced: lanes = rows), hidden behind dots
        float xz = 0.f, xr = 0.f, xh = 0.f, h0o = 0.f, h1o = 0.f;
        if (t < T_STEPS) {
            size_t xb = ((size_t)t * G3 + ug) * BATCH + rg;
            xz = __ldg(&g_xg0[xb]);
            xr = __ldg(&g_xg0[xb + 512 * BATCH]);
            xh = __ldg(&g_xg0[xb + 1024 * BATCH]);
            h0o = __ldcg(h0in + rg * 512 + ug);
        }
        if (t >= 1) h1o = __ldcg(h1in + rg * 512 + ug);
        __syncthreads();

        // ---- 9 dots over 4 chunks of 128 k ----
        u64 acc[9] = {};
#pragma unroll
        for (int kc = 0; kc < 4; ++kc) {
            // stage next chunk into the other buffer (overlaps dots below)
            if (kc < 3) {
                float4 v[8];
#pragma unroll
                for (int j = 0; j < 8; ++j) {
                    int idx = tid + j * TPB;
                    int arr = idx >> 10, w = idx & 1023;
                    int row = w >> 5, k4 = w & 31;
                    const float* src = (arr ? h1in : h0in) +
                                       (rbase + row) * 512 + (kc + 1) * 128 + k4 * 4;
                    v[j] = __ldcg((const float4*)src);
                }
#pragma unroll
                for (int j = 0; j < 8; ++j) {
                    int idx = tid + j * TPB;
                    int arr = idx >> 10, w = idx & 1023;
                    int row = w >> 5, k4 = w & 31;
                    *(float4*)&(arr ? hb1[(kc + 1) & 1]
                                    : hb0[(kc + 1) & 1])[row * HCH + k4 * 4] = v[j];
                }
            }

            const float* hp0 = hb0[kc & 1] + r_loc * HCH;
            const float* hp1 = hb1[kc & 1] + r_loc * HCH;
            const float* wk  = wcol + kc * 128;
#pragma unroll 2
            for (int kk = 0; kk < 128; kk += 4) {
                ulonglong2 a0 = *(const ulonglong2*)(hp0 + kk);
                ulonglong2 a1 = *(const ulonglong2*)(hp1 + kk);
#pragma unroll
                for (int j = 0; j < 9; ++j) {
                    ulonglong2 w = *(const ulonglong2*)(wk + j * WKS + kk);
                    u64 lo = (j >= 3 && j < 6) ? a1.x : a0.x;
                    u64 hi = (j >= 3 && j < 6) ? a1.y : a0.y;
                    FMA2(acc[j], lo, w.x);
                    FMA2(acc[j], hi, w.y);
                }
            }
            __syncthreads();
        }

        // ---- pointwise layer 0: h0(t) ----
        if (t < T_STEPS) {
            float az = sum2(acc[0]), ar = sum2(acc[1]), ah = sum2(acc[2]);
            float z    = sigf(xz + az + br0z);
            float rgt  = sigf(xr + ar + br0r);
            float cand = tanhf(xh + rgt * (ah + br0h));
            h0out[rg * 512 + ug] = z * h0o + (1.f - z) * cand;
        }

        // ---- pointwise layer 1: h1(t-1) ----
        if (t >= 1) {
            float cz = sum2(acc[3]), cr = sum2(acc[4]), ch = sum2(acc[5]);
            float bz = sum2(acc[6]), brr = sum2(acc[7]), bh = sum2(acc[8]);
            float z1    = sigf(bz + bi1z + cz + br1z);
            float r1    = sigf(brr + bi1r + cr + br1r);
            float cand1 = tanhf(bh + bi1h + r1 * (ch + br1h));
            float h1n   = z1 * h1o + (1.f - z1) * cand1;
            h1out[rg * 512 + ug] = h1n;
            if (t == T_STEPS) out[rg * 512 + ug] = h1n;
        }

        gbar(++gen);
    }
}

// ---------------- launcher ----------------
extern "C" void kernel_launch(void* const* d_in, const int* in_sizes, int n_in,
                              void* d_out, int out_size) {
    const float* x  = (const float*)d_in[0];
    const float* W0 = (const float*)d_in[1];
    const float* U0 = (const float*)d_in[2];
    const float* b0 = (const float*)d_in[3];
    const float* W1 = (const float*)d_in[4];
    const float* U1 = (const float*)d_in[5];
    const float* b1 = (const float*)d_in[6];
    float* out = (float*)d_out;

    cudaFuncSetAttribute(gru_loop, cudaFuncAttributeMaxDynamicSharedMemorySize,
                         SMEM_BYTES);

    // 3 dummies so ncu -s 5 lands on gru_loop (launch #6)
    nop_kernel<<<1, 32>>>(0);
    nop_kernel<<<1, 32>>>(0);
    nop_kernel<<<1, 32>>>(0);
    reset_kernel<<<32, 256>>>();
    precompute_xg0<<<dim3(24, 1024), TPB>>>(x, W0, b0);
    gru_loop<<<NCTA, TPB, SMEM_BYTES>>>(U0, W1, U1, b0, b1, out);
}